// round 11
// baseline (speedup 1.0000x reference)
#include <cuda_runtime.h>
#include <cstdint>
#include <math.h>

// Problem constants (fixed by the reference)
#define B_      8
#define HQ_     32
#define HK_     8
#define D_      64
#define S_      32
#define NB_     128
#define W_      1024
#define G_      (HQ_ / HK_)     // 4 q heads per kv head

#define NSPLIT  8
#define NWARPS  4
#define NTHREADS (NWARPS * 32)
#define SP      32              // positions per stage
#define NBUF    3               // smem stage buffers

// float4-unit strides in the cache [P, 2, Hk, S, D]:
#define PG4   8192      // 2*HK*S*D/4
#define HK4   512       // S*D/4
#define VP4   4096      // HK*S*D/4

// Split-KV scratch (no cudaMalloc allowed)
__device__ float g_l[B_ * HQ_ * NSPLIT];
__device__ float g_acc[B_ * HQ_ * NSPLIT * D_];
__device__ int   g_cnt[B_ * HK_];                 // zero-init; self-resetting

#define CP_ASYNC16(dst_u32, src_ptr) \
    asm volatile("cp.async.cg.shared.global [%0], [%1], 16;\n" \
                 :: "r"(dst_u32), "l"(src_ptr))
#define CP_COMMIT()  asm volatile("cp.async.commit_group;\n" ::: "memory")

__device__ __forceinline__ float dot8(float4 qa, float4 qb, float4 ka, float4 kb)
{
    return qa.x*ka.x + qa.y*ka.y + qa.z*ka.z + qa.w*ka.w
         + qb.x*kb.x + qb.y*kb.y + qb.z*kb.z + qb.w*kb.w;
}

__global__ __launch_bounds__(NTHREADS)
void attn_fused_kernel(const float* __restrict__ q_last,
                       const float* __restrict__ k_last,
                       const float* __restrict__ v_last,
                       const float* __restrict__ cache,
                       const int*   __restrict__ block_ids,
                       const int*   __restrict__ start_pos,
                       const float* __restrict__ sink,
                       float*       __restrict__ out)
{
    const int b     = blockIdx.x;
    const int hk    = blockIdx.y;
    const int split = blockIdx.z;
    const int tid   = threadIdx.x;
    const int w     = tid >> 5;
    const int lane  = tid & 31;
    const int e     = lane & 7;        // 8 lanes cover a D=64 row (2x float4)
    const int q4    = lane >> 3;       // quad id within warp

    const int pos = start_pos[b];
    const int t0  = max(0, pos - W_ + 1);
    const int L   = pos - t0 + 1;
    const int chunk = (L + NSPLIT - 1) / NSPLIT;   // <= 128
    const int ts  = t0 + split * chunk;
    const int te  = min(ts + chunk, pos + 1);
    const int te2 = min(te, pos);      // main loop excludes t == pos

    const float4* cache4 = (const float4*)cache;
    const int*    bid    = block_ids + b * NB_;

    // chunk <= 128 positions spans at most 5 pages: preload ids into regs
    const int bp = ts >> 5;
    const int p0 = bid[min(bp + 0, NB_ - 1)];
    const int p1 = bid[min(bp + 1, NB_ - 1)];
    const int p2 = bid[min(bp + 2, NB_ - 1)];
    const int p3 = bid[min(bp + 3, NB_ - 1)];
    const int p4 = bid[min(bp + 4, NB_ - 1)];

    // q for the G grouped heads, pre-scaled by 1/sqrt(64)
    float4 qa[G_], qb[G_];
#pragma unroll
    for (int g = 0; g < G_; g++) {
        const float4* qr = (const float4*)(q_last + ((size_t)(b * HQ_ + hk * G_ + g)) * D_);
        float4 a = qr[e], bb = qr[e + 8];
        qa[g] = make_float4(a.x*0.125f,  a.y*0.125f,  a.z*0.125f,  a.w*0.125f);
        qb[g] = make_float4(bb.x*0.125f, bb.y*0.125f, bb.z*0.125f, bb.w*0.125f);
    }

    float  l[G_];
    float4 acca[G_], accb[G_];
#pragma unroll
    for (int g = 0; g < G_; g++) {
        l[g] = 0.f;
        acca[g] = make_float4(0.f,0.f,0.f,0.f);
        accb[g] = make_float4(0.f,0.f,0.f,0.f);
    }

    const int khk = hk * HK4;

    // Stage buffers: [buf][position 0..31][32 float4: 16 K-row + 16 V-row]
    __shared__ float4 kvs[NBUF][SP][32];

    const int nst = (te2 > ts) ? ((te2 - ts + SP - 1) >> 5) : 0;

    // issue one 32-position stage (16 KB) CTA-cooperatively: 8 cp.async/thread
    auto issue = [&](int s) {
        const int base_t = ts + s * SP;
        float4* dstbuf = &kvs[s % NBUF][0][0];
#pragma unroll
        for (int k = 0; k < 8; k++) {
            const int flat = k * NTHREADS + tid;   // 0..1023
            const int p    = flat >> 5;            // position in stage
            const int j    = flat & 31;            // float4 slot (K:0-15, V:16-31)
            const int tc   = min(base_t + p, te2 - 1);
            const int jj   = (tc >> 5) - bp;
            const int pg   = (jj == 0) ? p0 : (jj == 1) ? p1 : (jj == 2) ? p2
                           : (jj == 3) ? p3 : p4;
            const int src  = pg * PG4 + khk + (tc & 31) * 16
                           + ((j < 16) ? j : (VP4 + j - 16));
            const uint32_t dst =
                (uint32_t)__cvta_generic_to_shared(dstbuf + flat);
            CP_ASYNC16(dst, cache4 + src);
        }
        CP_COMMIT();
    };

    // ---- software pipeline: depth 2 in flight, 3 buffers ----
    if (nst > 0) issue(0);
    if (nst > 1) issue(1);

    for (int s = 0; s < nst; s++) {
        if (s + 2 < nst) issue(s + 2);
        const int pend = min(nst, s + 3) - s - 1;  // groups allowed pending
        if (pend == 2)      asm volatile("cp.async.wait_group 2;\n" ::: "memory");
        else if (pend == 1) asm volatile("cp.async.wait_group 1;\n" ::: "memory");
        else                asm volatile("cp.async.wait_group 0;\n" ::: "memory");
        __syncthreads();                           // stage s visible CTA-wide

        const float4 (*buf)[32] = kvs[s % NBUF];
        const int pA = (w << 3) + q4;              // this warp's quad-A position
        const int sgb = ts + s * SP;
        const bool vA = (sgb + pA)     < te2;
        const bool vB = (sgb + pA + 4) < te2;

        // K first: score phase
        const float4 kaA = buf[pA][e],     kbA = buf[pA][e + 8];
        const float4 kaB = buf[pA + 4][e], kbB = buf[pA + 4][e + 8];

        float sA[G_], sB[G_];
#pragma unroll
        for (int g = 0; g < G_; g++) {
            sA[g] = dot8(qa[g], qb[g], kaA, kbA);
            sB[g] = dot8(qa[g], qb[g], kaB, kbB);
        }
#pragma unroll
        for (int off = 4; off >= 1; off >>= 1) {
#pragma unroll
            for (int g = 0; g < G_; g++) {
                sA[g] += __shfl_xor_sync(0xffffffffu, sA[g], off);
                sB[g] += __shfl_xor_sync(0xffffffffu, sB[g], off);
            }
        }

        // V second: accumulate phase (keeps peak live float4 count low)
        const float4 vaA = buf[pA][16 + e],     vbA = buf[pA][24 + e];
        const float4 vaB = buf[pA + 4][16 + e], vbB = buf[pA + 4][24 + e];
#pragma unroll
        for (int g = 0; g < G_; g++) {
            const float pAw = vA ? __expf(sA[g]) : 0.f;
            const float pBw = vB ? __expf(sB[g]) : 0.f;
            l[g] += pAw + pBw;
            acca[g].x += pAw * vaA.x + pBw * vaB.x;
            acca[g].y += pAw * vaA.y + pBw * vaB.y;
            acca[g].z += pAw * vaA.z + pBw * vaB.z;
            acca[g].w += pAw * vaA.w + pBw * vaB.w;
            accb[g].x += pAw * vbA.x + pBw * vbB.x;
            accb[g].y += pAw * vbA.y + pBw * vbB.y;
            accb[g].z += pAw * vbA.z + pBw * vbB.z;
            accb[g].w += pAw * vbA.w + pBw * vbB.w;
        }
        __syncthreads();                           // done reading buf before reuse
    }

    // ---- t == pos handled once, by warp 0 / lane-group 0 of the owning split ----
    if (pos >= ts && pos < te && w == 0 && lane < 8) {
        const float4* kr = (const float4*)(k_last + ((size_t)(b * HK_ + hk)) * D_);
        const float4* vr = (const float4*)(v_last + ((size_t)(b * HK_ + hk)) * D_);
        const float4 ka = kr[e], kb = kr[e + 8];
        const float4 va = vr[e], vb = vr[e + 8];
        float s[G_];
#pragma unroll
        for (int g = 0; g < G_; g++) s[g] = dot8(qa[g], qb[g], ka, kb);
#pragma unroll
        for (int off = 4; off >= 1; off >>= 1) {
#pragma unroll
            for (int g = 0; g < G_; g++)
                s[g] += __shfl_xor_sync(0x000000ffu, s[g], off);
        }
#pragma unroll
        for (int g = 0; g < G_; g++) {
            const float p = __expf(s[g]);
            l[g] += p;
            acca[g].x += p * va.x; acca[g].y += p * va.y;
            acca[g].z += p * va.z; acca[g].w += p * va.w;
            accb[g].x += p * vb.x; accb[g].y += p * vb.y;
            accb[g].z += p * vb.z; accb[g].w += p * vb.w;
        }
    }

    // ---- merge the 4 lane-groups of each warp (pure sums, no max) ----
#pragma unroll
    for (int g = 0; g < G_; g++) {
#pragma unroll
        for (int off = 8; off <= 16; off <<= 1) {
            l[g]      += __shfl_xor_sync(0xffffffffu, l[g], off);
            acca[g].x += __shfl_xor_sync(0xffffffffu, acca[g].x, off);
            acca[g].y += __shfl_xor_sync(0xffffffffu, acca[g].y, off);
            acca[g].z += __shfl_xor_sync(0xffffffffu, acca[g].z, off);
            acca[g].w += __shfl_xor_sync(0xffffffffu, acca[g].w, off);
            accb[g].x += __shfl_xor_sync(0xffffffffu, accb[g].x, off);
            accb[g].y += __shfl_xor_sync(0xffffffffu, accb[g].y, off);
            accb[g].z += __shfl_xor_sync(0xffffffffu, accb[g].z, off);
            accb[g].w += __shfl_xor_sync(0xffffffffu, accb[g].w, off);
        }
    }

    // ---- cross-warp combine via smem ----
    __shared__ float sl_[NWARPS][G_];
    __shared__ float sa_[NWARPS][G_][D_];
    if (lane < 8) {
#pragma unroll
        for (int g = 0; g < G_; g++) {
            ((float4*)sa_[w][g])[e]     = acca[g];
            ((float4*)sa_[w][g])[e + 8] = accb[g];
        }
    }
    if (lane == 0) {
#pragma unroll
        for (int g = 0; g < G_; g++) sl_[w][g] = l[g];
    }
    __syncthreads();

#pragma unroll
    for (int rep = 0; rep < 2; rep++) {
        const int i = tid + rep * NTHREADS;        // 0..255 -> (g,d)
        const int g = i >> 6;
        const int d = i & 63;
        float Lt = 0.f, A = 0.f;
#pragma unroll
        for (int ww = 0; ww < NWARPS; ww++) {
            Lt += sl_[ww][g];
            A  += sa_[ww][g][d];
        }
        const int idx = ((b * HK_ + hk) * G_ + g) * NSPLIT + split;
        if (d == 0) g_l[idx] = Lt;
        g_acc[idx * D_ + d] = A;
    }

    // ---- split-KV finalization: last CTA per (b,hk) reduces ----
    __shared__ int is_last;
    __threadfence();
    __syncthreads();
    if (tid == 0) {
        const int old = atomicAdd(&g_cnt[b * HK_ + hk], 1);
        is_last = (old == NSPLIT - 1);
    }
    __syncthreads();
    if (!is_last) return;
    __threadfence();

#pragma unroll
    for (int rep = 0; rep < 2; rep++) {
        const int i = tid + rep * NTHREADS;
        const int g = i >> 6;
        const int d = i & 63;
        const int hq = hk * G_ + g;
        const int base = ((b * HK_ + hk) * G_ + g) * NSPLIT;

        float Lt = __expf(sink[hq]);               // sink mass, denominator only
        float A  = 0.f;
#pragma unroll
        for (int s = 0; s < NSPLIT; s++) {
            Lt += g_l[base + s];
            A  += g_acc[(base + s) * D_ + d];
        }
        out[((size_t)(b * HQ_ + hq)) * D_ + d] = A / Lt;
    }
    if (tid == 0) g_cnt[b * HK_ + hk] = 0;         // reset for next graph replay
}

extern "C" void kernel_launch(void* const* d_in, const int* in_sizes, int n_in,
                              void* d_out, int out_size)
{
    const float* q_last     = (const float*)d_in[0];
    const float* k_last     = (const float*)d_in[1];
    const float* v_last     = (const float*)d_in[2];
    const float* cache      = (const float*)d_in[3];
    const int*   block_ids  = (const int*)d_in[4];
    const int*   start_pos  = (const int*)d_in[5];
    const float* sink       = (const float*)d_in[6];
    float*       out        = (float*)d_out;

    dim3 grid(B_, HK_, NSPLIT);
    attn_fused_kernel<<<grid, NTHREADS>>>(q_last, k_last, v_last, cache,
                                          block_ids, start_pos, sink, out);
}

// round 13
// speedup vs baseline: 1.0021x; 1.0021x over previous
#include <cuda_runtime.h>
#include <cstdint>
#include <math.h>

// Problem constants (fixed by the reference)
#define B_      8
#define HQ_     32
#define HK_     8
#define D_      64
#define S_      32
#define NB_     128
#define W_      1024
#define G_      (HQ_ / HK_)     // 4 q heads per kv head

#define NSPLIT  8
#define NWARPS  4
#define NTHREADS (NWARPS * 32)
#define NBUF    3               // stage buffers (1 page = 16 KB each)

// float4-unit strides in the cache [P, 2, Hk, S, D]:
#define PG4   8192      // 2*HK*S*D/4
#define HK4   512       // S*D/4
#define VP4   4096      // HK*S*D/4

// Split-KV scratch (no cudaMalloc allowed)
__device__ float g_l[B_ * HQ_ * NSPLIT];
__device__ float g_acc[B_ * HQ_ * NSPLIT * D_];
__device__ int   g_cnt[B_ * HK_];                 // zero-init; self-resetting

__device__ __forceinline__ float dot8(float4 qa, float4 qb, float4 ka, float4 kb)
{
    return qa.x*ka.x + qa.y*ka.y + qa.z*ka.z + qa.w*ka.w
         + qb.x*kb.x + qb.y*kb.y + qb.z*kb.z + qb.w*kb.w;
}

__global__ __launch_bounds__(NTHREADS)
void attn_fused_kernel(const float* __restrict__ q_last,
                       const float* __restrict__ k_last,
                       const float* __restrict__ v_last,
                       const float* __restrict__ cache,
                       const int*   __restrict__ block_ids,
                       const int*   __restrict__ start_pos,
                       const float* __restrict__ sink,
                       float*       __restrict__ out)
{
    const int b     = blockIdx.x;
    const int hk    = blockIdx.y;
    const int split = blockIdx.z;
    const int tid   = threadIdx.x;
    const int w     = tid >> 5;
    const int lane  = tid & 31;
    const int e     = lane & 7;        // 8 lanes cover a D=64 row (2x float4)
    const int q4    = lane >> 3;       // quad id within warp

    const int pos = start_pos[b];
    const int t0  = max(0, pos - W_ + 1);
    const int L   = pos - t0 + 1;
    const int chunk = (L + NSPLIT - 1) / NSPLIT;   // <= 128
    const int ts  = t0 + split * chunk;
    const int te  = min(ts + chunk, pos + 1);
    const int te2 = min(te, pos);      // main loop excludes t == pos

    const float4* cache4 = (const float4*)cache;
    const int*    bid    = block_ids + b * NB_;

    // chunk <= 128 positions spans at most 5 pages: preload ids into regs
    const int bp = ts >> 5;
    const int p0 = bid[min(bp + 0, NB_ - 1)];
    const int p1 = bid[min(bp + 1, NB_ - 1)];
    const int p2 = bid[min(bp + 2, NB_ - 1)];
    const int p3 = bid[min(bp + 3, NB_ - 1)];
    const int p4 = bid[min(bp + 4, NB_ - 1)];

    // q for the G grouped heads, pre-scaled by 1/sqrt(64)
    float4 qa[G_], qb[G_];
#pragma unroll
    for (int g = 0; g < G_; g++) {
        const float4* qr = (const float4*)(q_last + ((size_t)(b * HQ_ + hk * G_ + g)) * D_);
        float4 a = qr[e], bb = qr[e + 8];
        qa[g] = make_float4(a.x*0.125f,  a.y*0.125f,  a.z*0.125f,  a.w*0.125f);
        qb[g] = make_float4(bb.x*0.125f, bb.y*0.125f, bb.z*0.125f, bb.w*0.125f);
    }

    float  l[G_];
    float4 acca[G_], accb[G_];
#pragma unroll
    for (int g = 0; g < G_; g++) {
        l[g] = 0.f;
        acca[g] = make_float4(0.f,0.f,0.f,0.f);
        accb[g] = make_float4(0.f,0.f,0.f,0.f);
    }

    const int khk = hk * HK4;

    // Stage buffers: one full page per stage.
    // kvs[bu][0..511]    = K plane (32 pos x 16 float4, contiguous in GMEM)
    // kvs[bu][512..1023] = V plane
    __shared__ __align__(128) float4   kvs[NBUF][1024];
    __shared__ __align__(16)  uint64_t mbar[NBUF];

    const uint32_t mb0 = (uint32_t)__cvta_generic_to_shared(&mbar[0]);
    if (tid == 0) {
#pragma unroll
        for (int i = 0; i < NBUF; i++)
            asm volatile("mbarrier.init.shared.b64 [%0], 1;" :: "r"(mb0 + 8u*i) : "memory");
    }
    __syncthreads();

    // number of pages overlapping [ts, te2)
    const int nst = (te2 > ts) ? (((te2 - 1) >> 5) - bp + 1) : 0;

    // issue one page stage (16 KB) via two 8 KB bulk copies (TMA engine path)
    auto issue = [&](int s) {
        if (tid != 0) return;
        const int bu = s % NBUF;
        const int pg = (s == 0) ? p0 : (s == 1) ? p1 : (s == 2) ? p2
                     : (s == 3) ? p3 : p4;
        const uint32_t mb = mb0 + 8u * bu;
        asm volatile("mbarrier.arrive.expect_tx.shared.b64 _, [%0], %1;"
                     :: "r"(mb), "r"(16384u) : "memory");
        const float4*  srcK = cache4 + (pg * PG4 + khk);
        const uint32_t dstK = (uint32_t)__cvta_generic_to_shared(&kvs[bu][0]);
        asm volatile("cp.async.bulk.shared::cta.global.mbarrier::complete_tx::bytes "
                     "[%0], [%1], %2, [%3];"
                     :: "r"(dstK), "l"(srcK), "r"(8192u), "r"(mb) : "memory");
        const float4*  srcV = srcK + VP4;
        const uint32_t dstV = dstK + 8192u;
        asm volatile("cp.async.bulk.shared::cta.global.mbarrier::complete_tx::bytes "
                     "[%0], [%1], %2, [%3];"
                     :: "r"(dstV), "l"(srcV), "r"(8192u), "r"(mb) : "memory");
    };

    if (nst > 0) issue(0);
    if (nst > 1) issue(1);
    if (nst > 2) issue(2);

    for (int s = 0; s < nst; s++) {
        const int bu = s % NBUF;
        const uint32_t mb  = mb0 + 8u * bu;
        const uint32_t par = (uint32_t)((s / NBUF) & 1);
        asm volatile(
            "{\n\t"
            ".reg .pred P;\n"
            "W%=:\n\t"
            "mbarrier.try_wait.parity.acquire.cta.shared::cta.b64 P, [%0], %1;\n\t"
            "@P bra D%=;\n\t"
            "bra W%=;\n"
            "D%=:\n\t"
            "}"
            :: "r"(mb), "r"(par) : "memory");

        const float4* bufK = &kvs[bu][0];
        const float4* bufV = &kvs[bu][512];
        const int page_base = (bp + s) << 5;
        const int pA = (w << 3) + q4;          // slot of quad A in this page
        const int pB = pA + 4;                 // slot of quad B
        const int tA = page_base + pA;
        const int tB = page_base + pB;
        const bool vA = (tA >= ts) && (tA < te2);
        const bool vB = (tB >= ts) && (tB < te2);

        const float4 kaA = bufK[pA*16 + e], kbA = bufK[pA*16 + 8 + e];
        const float4 kaB = bufK[pB*16 + e], kbB = bufK[pB*16 + 8 + e];

        float sA[G_], sB[G_];
#pragma unroll
        for (int g = 0; g < G_; g++) {
            sA[g] = dot8(qa[g], qb[g], kaA, kbA);
            sB[g] = dot8(qa[g], qb[g], kaB, kbB);
        }
#pragma unroll
        for (int off = 4; off >= 1; off >>= 1) {
#pragma unroll
            for (int g = 0; g < G_; g++) {
                sA[g] += __shfl_xor_sync(0xffffffffu, sA[g], off);
                sB[g] += __shfl_xor_sync(0xffffffffu, sB[g], off);
            }
        }

        const float4 vaA = bufV[pA*16 + e], vbA = bufV[pA*16 + 8 + e];
        const float4 vaB = bufV[pB*16 + e], vbB = bufV[pB*16 + 8 + e];
#pragma unroll
        for (int g = 0; g < G_; g++) {
            const float pAw = vA ? __expf(sA[g]) : 0.f;
            const float pBw = vB ? __expf(sB[g]) : 0.f;
            l[g] += pAw + pBw;
            acca[g].x += pAw * vaA.x + pBw * vaB.x;
            acca[g].y += pAw * vaA.y + pBw * vaB.y;
            acca[g].z += pAw * vaA.z + pBw * vaB.z;
            acca[g].w += pAw * vaA.w + pBw * vaB.w;
            accb[g].x += pAw * vbA.x + pBw * vbB.x;
            accb[g].y += pAw * vbA.y + pBw * vbB.y;
            accb[g].z += pAw * vbA.z + pBw * vbB.z;
            accb[g].w += pAw * vbA.w + pBw * vbB.w;
        }
        __syncthreads();                      // done reading buffer before reuse
        if (s + NBUF < nst) issue(s + NBUF);
    }

    // ---- t == pos handled once, by warp 0 / lane-group 0 of the owning split ----
    if (pos >= ts && pos < te && w == 0 && lane < 8) {
        const float4* kr = (const float4*)(k_last + ((size_t)(b * HK_ + hk)) * D_);
        const float4* vr = (const float4*)(v_last + ((size_t)(b * HK_ + hk)) * D_);
        const float4 ka = kr[e], kb = kr[e + 8];
        const float4 va = vr[e], vb = vr[e + 8];
        float s[G_];
#pragma unroll
        for (int g = 0; g < G_; g++) s[g] = dot8(qa[g], qb[g], ka, kb);
#pragma unroll
        for (int off = 4; off >= 1; off >>= 1) {
#pragma unroll
            for (int g = 0; g < G_; g++)
                s[g] += __shfl_xor_sync(0x000000ffu, s[g], off);
        }
#pragma unroll
        for (int g = 0; g < G_; g++) {
            const float p = __expf(s[g]);
            l[g] += p;
            acca[g].x += p * va.x; acca[g].y += p * va.y;
            acca[g].z += p * va.z; acca[g].w += p * va.w;
            accb[g].x += p * vb.x; accb[g].y += p * vb.y;
            accb[g].z += p * vb.z; accb[g].w += p * vb.w;
        }
    }

    // ---- merge the 4 lane-groups of each warp (pure sums, no max) ----
#pragma unroll
    for (int g = 0; g < G_; g++) {
#pragma unroll
        for (int off = 8; off <= 16; off <<= 1) {
            l[g]      += __shfl_xor_sync(0xffffffffu, l[g], off);
            acca[g].x += __shfl_xor_sync(0xffffffffu, acca[g].x, off);
            acca[g].y += __shfl_xor_sync(0xffffffffu, acca[g].y, off);
            acca[g].z += __shfl_xor_sync(0xffffffffu, acca[g].z, off);
            acca[g].w += __shfl_xor_sync(0xffffffffu, acca[g].w, off);
            accb[g].x += __shfl_xor_sync(0xffffffffu, accb[g].x, off);
            accb[g].y += __shfl_xor_sync(0xffffffffu, accb[g].y, off);
            accb[g].z += __shfl_xor_sync(0xffffffffu, accb[g].z, off);
            accb[g].w += __shfl_xor_sync(0xffffffffu, accb[g].w, off);
        }
    }

    // ---- cross-warp combine via smem ----
    __shared__ __align__(16) float sl_[NWARPS][G_];
    __shared__ __align__(16) float sa_[NWARPS][G_][D_];
    if (lane < 8) {
#pragma unroll
        for (int g = 0; g < G_; g++) {
            ((float4*)sa_[w][g])[e]     = acca[g];
            ((float4*)sa_[w][g])[e + 8] = accb[g];
        }
    }
    if (lane == 0) {
#pragma unroll
        for (int g = 0; g < G_; g++) sl_[w][g] = l[g];
    }
    __syncthreads();

#pragma unroll
    for (int rep = 0; rep < 2; rep++) {
        const int i = tid + rep * NTHREADS;        // 0..255 -> (g,d)
        const int g = i >> 6;
        const int d = i & 63;
        float Lt = 0.f, A = 0.f;
#pragma unroll
        for (int ww = 0; ww < NWARPS; ww++) {
            Lt += sl_[ww][g];
            A  += sa_[ww][g][d];
        }
        const int idx = ((b * HK_ + hk) * G_ + g) * NSPLIT + split;
        if (d == 0) g_l[idx] = Lt;
        g_acc[idx * D_ + d] = A;
    }

    // ---- split-KV finalization: last CTA per (b,hk) reduces ----
    __shared__ int is_last;
    __threadfence();
    __syncthreads();
    if (tid == 0) {
        const int old = atomicAdd(&g_cnt[b * HK_ + hk], 1);
        is_last = (old == NSPLIT - 1);
    }
    __syncthreads();
    if (!is_last) return;
    __threadfence();

#pragma unroll
    for (int rep = 0; rep < 2; rep++) {
        const int i = tid + rep * NTHREADS;
        const int g = i >> 6;
        const int d = i & 63;
        const int hq = hk * G_ + g;
        const int base = ((b * HK_ + hk) * G_ + g) * NSPLIT;

        float Lt = __expf(sink[hq]);               // sink mass, denominator only
        float A  = 0.f;
#pragma unroll
        for (int s = 0; s < NSPLIT; s++) {
            Lt += g_l[base + s];
            A  += g_acc[(base + s) * D_ + d];
        }
        out[((size_t)(b * HQ_ + hq)) * D_ + d] = A / Lt;
    }
    if (tid == 0) g_cnt[b * HK_ + hk] = 0;         // reset for next graph replay
}

extern "C" void kernel_launch(void* const* d_in, const int* in_sizes, int n_in,
                              void* d_out, int out_size)
{
    const float* q_last     = (const float*)d_in[0];
    const float* k_last     = (const float*)d_in[1];
    const float* v_last     = (const float*)d_in[2];
    const float* cache      = (const float*)d_in[3];
    const int*   block_ids  = (const int*)d_in[4];
    const int*   start_pos  = (const int*)d_in[5];
    const float* sink       = (const float*)d_in[6];
    float*       out        = (float*)d_out;

    dim3 grid(B_, HK_, NSPLIT);
    attn_fused_kernel<<<grid, NTHREADS>>>(q_last, k_last, v_last, cache,
                                          block_ids, start_pos, sink, out);
}

// round 15
// speedup vs baseline: 1.1484x; 1.1460x over previous
#include <cuda_runtime.h>
#include <cstdint>
#include <math.h>

// Problem constants (fixed by the reference)
#define B_      8
#define HQ_     32
#define HK_     8
#define D_      64
#define S_      32
#define NB_     128
#define W_      1024
#define G_      (HQ_ / HK_)     // 4 q heads per kv head

#define GC      2               // heads handled per CTA (G_ / 2)
#define NSPLIT  8
#define NWARPS  4
#define NTHREADS (NWARPS * 32)

// float4-unit strides in the cache [P, 2, Hk, S, D]:
#define PG4   8192      // 2*HK*S*D/4
#define HK4   512       // S*D/4
#define VP4   4096      // HK*S*D/4

// Split-KV scratch (no cudaMalloc allowed)
// idx = (b*HQ + hq)*NSPLIT + split
__device__ float g_l[B_ * HQ_ * NSPLIT];
__device__ float g_acc[B_ * HQ_ * NSPLIT * D_];
__device__ int   g_cnt[B_ * HK_ * 2];             // per (b, hk-half); self-resetting

// 32-byte KV load: non-coherent + L2 evict-last (keeps KV L2-resident across
// graph replays). sm_103a requires .v4.b64 width for the evict_last modifier.
__device__ __forceinline__ void ld_el32(const float4* p, float4& a, float4& b)
{
    uint64_t x0, x1, x2, x3;
    asm("ld.global.nc.L2::evict_last.v4.b64 {%0,%1,%2,%3}, [%4];"
        : "=l"(x0), "=l"(x1), "=l"(x2), "=l"(x3) : "l"(p));
    a.x = __uint_as_float((uint32_t)x0); a.y = __uint_as_float((uint32_t)(x0 >> 32));
    a.z = __uint_as_float((uint32_t)x1); a.w = __uint_as_float((uint32_t)(x1 >> 32));
    b.x = __uint_as_float((uint32_t)x2); b.y = __uint_as_float((uint32_t)(x2 >> 32));
    b.z = __uint_as_float((uint32_t)x3); b.w = __uint_as_float((uint32_t)(x3 >> 32));
}

__device__ __forceinline__ float dot8(float4 qa, float4 qb, float4 ka, float4 kb)
{
    return qa.x*ka.x + qa.y*ka.y + qa.z*ka.z + qa.w*ka.w
         + qb.x*kb.x + qb.y*kb.y + qb.z*kb.z + qb.w*kb.w;
}

__global__ __launch_bounds__(NTHREADS)
void attn_fused_kernel(const float* __restrict__ q_last,
                       const float* __restrict__ k_last,
                       const float* __restrict__ v_last,
                       const float* __restrict__ cache,
                       const int*   __restrict__ block_ids,
                       const int*   __restrict__ start_pos,
                       const float* __restrict__ sink,
                       float*       __restrict__ out)
{
    const int b     = blockIdx.x;
    const int hk2   = blockIdx.y;      // 0..15: (hk, head-half)
    const int hk    = hk2 >> 1;
    const int gh    = (hk2 & 1) * GC;  // first grouped head of this CTA
    const int split = blockIdx.z;
    const int tid   = threadIdx.x;
    const int w     = tid >> 5;
    const int lane  = tid & 31;
    const int e     = lane & 7;        // 8 lanes cover a D=64 row (32B each)
    const int q4    = lane >> 3;       // quad id within warp

    const int pos = start_pos[b];
    const int t0  = max(0, pos - W_ + 1);
    const int L   = pos - t0 + 1;
    const int chunk = (L + NSPLIT - 1) / NSPLIT;   // <= 128
    const int ts  = t0 + split * chunk;
    const int te  = min(ts + chunk, pos + 1);
    const int te2 = min(te, pos);      // main loop excludes t == pos

    const float4* cache4 = (const float4*)cache;
    const int*    bid    = block_ids + b * NB_;

    // chunk <= 128 positions spans at most 5 pages: preload ids into regs
    const int bp = ts >> 5;
    const int p0 = bid[min(bp + 0, NB_ - 1)];
    const int p1 = bid[min(bp + 1, NB_ - 1)];
    const int p2 = bid[min(bp + 2, NB_ - 1)];
    const int p3 = bid[min(bp + 3, NB_ - 1)];
    const int p4 = bid[min(bp + 4, NB_ - 1)];

    // q for this CTA's GC heads, pre-scaled by 1/sqrt(64).
    // Lane e owns float4 slices 2e and 2e+1 (contiguous 32 B).
    float4 qa[GC], qb[GC];
#pragma unroll
    for (int g = 0; g < GC; g++) {
        const float4* qr = (const float4*)(q_last +
                          ((size_t)(b * HQ_ + hk * G_ + gh + g)) * D_);
        float4 a = qr[2*e], bb = qr[2*e + 1];
        qa[g] = make_float4(a.x*0.125f,  a.y*0.125f,  a.z*0.125f,  a.w*0.125f);
        qb[g] = make_float4(bb.x*0.125f, bb.y*0.125f, bb.z*0.125f, bb.w*0.125f);
    }

    float  l[GC];
    float4 acca[GC], accb[GC];
#pragma unroll
    for (int g = 0; g < GC; g++) {
        l[g] = 0.f;
        acca[g] = make_float4(0.f,0.f,0.f,0.f);
        accb[g] = make_float4(0.f,0.f,0.f,0.f);
    }

    const int khk = hk * HK4;

    // ---- main loop: 8 positions per warp-iteration, all loads front-batched ----
    for (int wb = ts + (w << 3); wb < te2; wb += NWARPS * 8) {
        const int tA = wb + q4;            // quad A positions
        const int tB = wb + 4 + q4;        // quad B positions
        const bool vA = tA < te2;
        const bool vB = tB < te2;
        const int tcA = vA ? tA : (te2 - 1);
        const int tcB = vB ? tB : (te2 - 1);
        const int jA = (tcA >> 5) - bp;
        const int jB = (tcB >> 5) - bp;
        const int pgA = (jA == 0) ? p0 : (jA == 1) ? p1 : (jA == 2) ? p2
                      : (jA == 3) ? p3 : p4;
        const int pgB = (jB == 0) ? p0 : (jB == 1) ? p1 : (jB == 2) ? p2
                      : (jB == 3) ? p3 : p4;
        const int iA = pgA * PG4 + khk + (tcA & 31) * 16 + 2*e;
        const int iB = pgB * PG4 + khk + (tcB & 31) * 16 + 2*e;

        // 4 independent 32B loads per lane, L2 evict-last
        float4 kaA, kbA, vaA, vbA, kaB, kbB, vaB, vbB;
        ld_el32(cache4 + iA,       kaA, kbA);
        ld_el32(cache4 + iA + VP4, vaA, vbA);
        ld_el32(cache4 + iB,       kaB, kbB);
        ld_el32(cache4 + iB + VP4, vaB, vbB);

        float sA[GC], sB[GC];
#pragma unroll
        for (int g = 0; g < GC; g++) {
            sA[g] = dot8(qa[g], qb[g], kaA, kbA);
            sB[g] = dot8(qa[g], qb[g], kaB, kbB);
        }
#pragma unroll
        for (int off = 4; off >= 1; off >>= 1) {
#pragma unroll
            for (int g = 0; g < GC; g++) {
                sA[g] += __shfl_xor_sync(0xffffffffu, sA[g], off);
                sB[g] += __shfl_xor_sync(0xffffffffu, sB[g], off);
            }
        }
#pragma unroll
        for (int g = 0; g < GC; g++) {
            const float pA = vA ? __expf(sA[g]) : 0.f;
            const float pB = vB ? __expf(sB[g]) : 0.f;
            l[g] += pA + pB;
            acca[g].x += pA * vaA.x + pB * vaB.x;
            acca[g].y += pA * vaA.y + pB * vaB.y;
            acca[g].z += pA * vaA.z + pB * vaB.z;
            acca[g].w += pA * vaA.w + pB * vaB.w;
            accb[g].x += pA * vbA.x + pB * vbB.x;
            accb[g].y += pA * vbA.y + pB * vbB.y;
            accb[g].z += pA * vbA.z + pB * vbB.z;
            accb[g].w += pA * vbA.w + pB * vbB.w;
        }
    }

    // ---- t == pos handled once, by warp 0 / lane-group 0 of the owning split ----
    if (pos >= ts && pos < te && w == 0 && lane < 8) {
        const float4* kr = (const float4*)(k_last + ((size_t)(b * HK_ + hk)) * D_);
        const float4* vr = (const float4*)(v_last + ((size_t)(b * HK_ + hk)) * D_);
        const float4 ka = kr[2*e], kb = kr[2*e + 1];
        const float4 va = vr[2*e], vb = vr[2*e + 1];
        float s[GC];
#pragma unroll
        for (int g = 0; g < GC; g++) s[g] = dot8(qa[g], qb[g], ka, kb);
#pragma unroll
        for (int off = 4; off >= 1; off >>= 1) {
#pragma unroll
            for (int g = 0; g < GC; g++)
                s[g] += __shfl_xor_sync(0x000000ffu, s[g], off);
        }
#pragma unroll
        for (int g = 0; g < GC; g++) {
            const float p = __expf(s[g]);
            l[g] += p;
            acca[g].x += p * va.x; acca[g].y += p * va.y;
            acca[g].z += p * va.z; acca[g].w += p * va.w;
            accb[g].x += p * vb.x; accb[g].y += p * vb.y;
            accb[g].z += p * vb.z; accb[g].w += p * vb.w;
        }
    }

    // ---- merge the 4 lane-groups of each warp (pure sums, no max) ----
#pragma unroll
    for (int g = 0; g < GC; g++) {
#pragma unroll
        for (int off = 8; off <= 16; off <<= 1) {
            l[g]      += __shfl_xor_sync(0xffffffffu, l[g], off);
            acca[g].x += __shfl_xor_sync(0xffffffffu, acca[g].x, off);
            acca[g].y += __shfl_xor_sync(0xffffffffu, acca[g].y, off);
            acca[g].z += __shfl_xor_sync(0xffffffffu, acca[g].z, off);
            acca[g].w += __shfl_xor_sync(0xffffffffu, acca[g].w, off);
            accb[g].x += __shfl_xor_sync(0xffffffffu, accb[g].x, off);
            accb[g].y += __shfl_xor_sync(0xffffffffu, accb[g].y, off);
            accb[g].z += __shfl_xor_sync(0xffffffffu, accb[g].z, off);
            accb[g].w += __shfl_xor_sync(0xffffffffu, accb[g].w, off);
        }
    }

    // ---- cross-warp combine via smem ----
    __shared__ __align__(16) float sl_[NWARPS][GC];
    __shared__ __align__(16) float sa_[NWARPS][GC][D_];
    if (lane < 8) {
#pragma unroll
        for (int g = 0; g < GC; g++) {
            ((float4*)sa_[w][g])[2*e]     = acca[g];
            ((float4*)sa_[w][g])[2*e + 1] = accb[g];
        }
    }
    if (lane == 0) {
#pragma unroll
        for (int g = 0; g < GC; g++) sl_[w][g] = l[g];
    }
    __syncthreads();

    {
        const int g = tid >> 6;            // 0..1
        const int d = tid & 63;
        float Lt = 0.f, A = 0.f;
#pragma unroll
        for (int ww = 0; ww < NWARPS; ww++) {
            Lt += sl_[ww][g];
            A  += sa_[ww][g][d];
        }
        const int hq = hk * G_ + gh + g;
        const int idx = (b * HQ_ + hq) * NSPLIT + split;
        if (d == 0) g_l[idx] = Lt;
        g_acc[idx * D_ + d] = A;
    }

    // ---- split-KV finalization: last CTA per (b,hk2) reduces its 2 heads ----
    __shared__ int is_last;
    __threadfence();
    __syncthreads();
    if (tid == 0) {
        const int old = atomicAdd(&g_cnt[b * (HK_ * 2) + hk2], 1);
        is_last = (old == NSPLIT - 1);
    }
    __syncthreads();
    if (!is_last) return;
    __threadfence();

    {
        const int g = tid >> 6;
        const int d = tid & 63;
        const int hq = hk * G_ + gh + g;
        const int base = (b * HQ_ + hq) * NSPLIT;

        float Lt = __expf(sink[hq]);               // sink mass, denominator only
        float A  = 0.f;
#pragma unroll
        for (int s = 0; s < NSPLIT; s++) {
            Lt += g_l[base + s];
            A  += g_acc[(base + s) * D_ + d];
        }
        out[((size_t)(b * HQ_ + hq)) * D_ + d] = A / Lt;
    }
    if (tid == 0) g_cnt[b * (HK_ * 2) + hk2] = 0;  // reset for next graph replay
}

extern "C" void kernel_launch(void* const* d_in, const int* in_sizes, int n_in,
                              void* d_out, int out_size)
{
    const float* q_last     = (const float*)d_in[0];
    const float* k_last     = (const float*)d_in[1];
    const float* v_last     = (const float*)d_in[2];
    const float* cache      = (const float*)d_in[3];
    const int*   block_ids  = (const int*)d_in[4];
    const int*   start_pos  = (const int*)d_in[5];
    const float* sink       = (const float*)d_in[6];
    float*       out        = (float*)d_out;

    dim3 grid(B_, HK_ * 2, NSPLIT);
    attn_fused_kernel<<<grid, NTHREADS>>>(q_last, k_last, v_last, cache,
                                          block_ids, start_pos, sink, out);
}

// round 16
// speedup vs baseline: 1.2196x; 1.0620x over previous
#include <cuda_runtime.h>
#include <cstdint>
#include <math.h>

// Problem constants (fixed by the reference)
#define B_      8
#define HQ_     32
#define HK_     8
#define D_      64
#define S_      32
#define NB_     128
#define W_      1024
#define G_      (HQ_ / HK_)     // 4 q heads per kv head

#define GC      2               // heads handled per CTA (G_ / 2)
#define NWARPS  16
#define NTHREADS (NWARPS * 32)  // 512

// float4-unit strides in the cache [P, 2, Hk, S, D]:
#define PG4   8192      // 2*HK*S*D/4
#define HK4   512       // S*D/4
#define VP4   4096      // HK*S*D/4

__device__ __forceinline__ float dot8(float4 qa, float4 qb, float4 ka, float4 kb)
{
    return qa.x*ka.x + qa.y*ka.y + qa.z*ka.z + qa.w*ka.w
         + qb.x*kb.x + qb.y*kb.y + qb.z*kb.z + qb.w*kb.w;
}

__global__ __launch_bounds__(NTHREADS)
void attn_onepass_kernel(const float* __restrict__ q_last,
                         const float* __restrict__ k_last,
                         const float* __restrict__ v_last,
                         const float* __restrict__ cache,
                         const int*   __restrict__ block_ids,
                         const int*   __restrict__ start_pos,
                         const float* __restrict__ sink,
                         float*       __restrict__ out)
{
    const int b    = blockIdx.x;
    const int hk   = blockIdx.y;
    const int gh   = blockIdx.z * GC;  // first grouped head of this CTA
    const int tid  = threadIdx.x;
    const int w    = tid >> 5;
    const int lane = tid & 31;
    const int e    = lane & 7;         // 8 lanes cover a D=64 row (2x float4)
    const int q4   = lane >> 3;        // quad id within warp

    const int pos = start_pos[b];
    const int t0  = max(0, pos - W_ + 1);
    const int te2 = pos;               // main loop excludes t == pos

    const float4* cache4 = (const float4*)cache;

    // page ids for this sequence -> smem (kills the dependent LDG on the
    // address path; LDS ~29cy and broadcast-friendly)
    __shared__ int spid[NB_];
    if (tid < NB_) spid[tid] = block_ids[b * NB_ + tid];

    // q for this CTA's GC heads, pre-scaled by 1/sqrt(64)
    float4 qa[GC], qb[GC];
#pragma unroll
    for (int g = 0; g < GC; g++) {
        const float4* qr = (const float4*)(q_last +
                          ((size_t)(b * HQ_ + hk * G_ + gh + g)) * D_);
        float4 a = qr[e], bb = qr[e + 8];
        qa[g] = make_float4(a.x*0.125f,  a.y*0.125f,  a.z*0.125f,  a.w*0.125f);
        qb[g] = make_float4(bb.x*0.125f, bb.y*0.125f, bb.z*0.125f, bb.w*0.125f);
    }

    float  l[GC];
    float4 acca[GC], accb[GC];
#pragma unroll
    for (int g = 0; g < GC; g++) {
        l[g] = 0.f;
        acca[g] = make_float4(0.f,0.f,0.f,0.f);
        accb[g] = make_float4(0.f,0.f,0.f,0.f);
    }

    const int khk = hk * HK4;
    __syncthreads();                   // spid ready

    // ---- main loop: 8 positions per warp-iteration, 16 warps cover 128/iter ----
    for (int wb = t0 + (w << 3); wb < te2; wb += NWARPS * 8) {
        const int tA = wb + q4;            // quad A positions
        const int tB = wb + 4 + q4;        // quad B positions
        const bool vA = tA < te2;
        const bool vB = tB < te2;
        const int tcA = vA ? tA : (te2 - 1);
        const int tcB = vB ? tB : (te2 - 1);
        const int iA = spid[tcA >> 5] * PG4 + khk + (tcA & 31) * 16 + e;
        const int iB = spid[tcB >> 5] * PG4 + khk + (tcB & 31) * 16 + e;

        // 8 independent LDG.128 per lane
        const float4 kaA = cache4[iA],       kbA = cache4[iA + 8];
        const float4 vaA = cache4[iA + VP4], vbA = cache4[iA + VP4 + 8];
        const float4 kaB = cache4[iB],       kbB = cache4[iB + 8];
        const float4 vaB = cache4[iB + VP4], vbB = cache4[iB + VP4 + 8];

        float sA[GC], sB[GC];
#pragma unroll
        for (int g = 0; g < GC; g++) {
            sA[g] = dot8(qa[g], qb[g], kaA, kbA);
            sB[g] = dot8(qa[g], qb[g], kaB, kbB);
        }
#pragma unroll
        for (int off = 4; off >= 1; off >>= 1) {
#pragma unroll
            for (int g = 0; g < GC; g++) {
                sA[g] += __shfl_xor_sync(0xffffffffu, sA[g], off);
                sB[g] += __shfl_xor_sync(0xffffffffu, sB[g], off);
            }
        }
#pragma unroll
        for (int g = 0; g < GC; g++) {
            const float pA = vA ? __expf(sA[g]) : 0.f;
            const float pB = vB ? __expf(sB[g]) : 0.f;
            l[g] += pA + pB;
            acca[g].x += pA * vaA.x + pB * vaB.x;
            acca[g].y += pA * vaA.y + pB * vaB.y;
            acca[g].z += pA * vaA.z + pB * vaB.z;
            acca[g].w += pA * vaA.w + pB * vaB.w;
            accb[g].x += pA * vbA.x + pB * vbB.x;
            accb[g].y += pA * vbA.y + pB * vbB.y;
            accb[g].z += pA * vbA.z + pB * vbB.z;
            accb[g].w += pA * vbA.w + pB * vbB.w;
        }
    }

    // ---- t == pos handled once (always within this CTA's range) ----
    if (w == 0 && lane < 8) {
        const float4* kr = (const float4*)(k_last + ((size_t)(b * HK_ + hk)) * D_);
        const float4* vr = (const float4*)(v_last + ((size_t)(b * HK_ + hk)) * D_);
        const float4 ka = kr[e], kb = kr[e + 8];
        const float4 va = vr[e], vb = vr[e + 8];
        float s[GC];
#pragma unroll
        for (int g = 0; g < GC; g++) s[g] = dot8(qa[g], qb[g], ka, kb);
#pragma unroll
        for (int off = 4; off >= 1; off >>= 1) {
#pragma unroll
            for (int g = 0; g < GC; g++)
                s[g] += __shfl_xor_sync(0x000000ffu, s[g], off);
        }
#pragma unroll
        for (int g = 0; g < GC; g++) {
            const float p = __expf(s[g]);
            l[g] += p;
            acca[g].x += p * va.x; acca[g].y += p * va.y;
            acca[g].z += p * va.z; acca[g].w += p * va.w;
            accb[g].x += p * vb.x; accb[g].y += p * vb.y;
            accb[g].z += p * vb.z; accb[g].w += p * vb.w;
        }
    }

    // ---- merge the 4 lane-groups of each warp (pure sums, no max) ----
#pragma unroll
    for (int g = 0; g < GC; g++) {
#pragma unroll
        for (int off = 8; off <= 16; off <<= 1) {
            l[g]      += __shfl_xor_sync(0xffffffffu, l[g], off);
            acca[g].x += __shfl_xor_sync(0xffffffffu, acca[g].x, off);
            acca[g].y += __shfl_xor_sync(0xffffffffu, acca[g].y, off);
            acca[g].z += __shfl_xor_sync(0xffffffffu, acca[g].z, off);
            acca[g].w += __shfl_xor_sync(0xffffffffu, acca[g].w, off);
            accb[g].x += __shfl_xor_sync(0xffffffffu, accb[g].x, off);
            accb[g].y += __shfl_xor_sync(0xffffffffu, accb[g].y, off);
            accb[g].z += __shfl_xor_sync(0xffffffffu, accb[g].z, off);
            accb[g].w += __shfl_xor_sync(0xffffffffu, accb[g].w, off);
        }
    }

    // ---- CTA-internal combine + direct output (no scratch / fence / atomic) ----
    __shared__ __align__(16) float sl_[NWARPS][GC];
    __shared__ __align__(16) float sa_[NWARPS][GC][D_];
    if (lane < 8) {
#pragma unroll
        for (int g = 0; g < GC; g++) {
            ((float4*)sa_[w][g])[e]     = acca[g];
            ((float4*)sa_[w][g])[e + 8] = accb[g];
        }
    }
    if (lane == 0) {
#pragma unroll
        for (int g = 0; g < GC; g++) sl_[w][g] = l[g];
    }
    __syncthreads();

    if (tid < GC * D_) {                   // 128 threads: (g,d)
        const int g = tid >> 6;
        const int d = tid & 63;
        float Lt = 0.f, A = 0.f;
#pragma unroll
        for (int ww = 0; ww < NWARPS; ww++) {
            Lt += sl_[ww][g];
            A  += sa_[ww][g][d];
        }
        const int hq = hk * G_ + gh + g;
        Lt += __expf(sink[hq]);            // sink mass, denominator only
        out[((size_t)(b * HQ_ + hq)) * D_ + d] = A / Lt;
    }
}

extern "C" void kernel_launch(void* const* d_in, const int* in_sizes, int n_in,
                              void* d_out, int out_size)
{
    const float* q_last     = (const float*)d_in[0];
    const float* k_last     = (const float*)d_in[1];
    const float* v_last     = (const float*)d_in[2];
    const float* cache      = (const float*)d_in[3];
    const int*   block_ids  = (const int*)d_in[4];
    const int*   start_pos  = (const int*)d_in[5];
    const float* sink       = (const float*)d_in[6];
    float*       out        = (float*)d_out;

    dim3 grid(B_, HK_, G_ / GC);           // (8, 8, 2) = 128 CTAs
    attn_onepass_kernel<<<grid, NTHREADS>>>(q_last, k_last, v_last, cache,
                                            block_ids, start_pos, sink, out);
}